// round 15
// baseline (speedup 1.0000x reference)
#include <cuda_runtime.h>
#include <cuda_fp16.h>
#include <cstdint>
#include <cstddef>
#include <math.h>

// ======================= device-global scratch (no allocs allowed) =======================
__device__ __align__(256) __half g_A[16777216];   // activations ping, 65536x256 max
__device__ __align__(256) __half g_B[16777216];   // activations pong
__device__ __align__(256) __half g_W[131072];     // WR_w fp16 [256,512]

// ======================= helpers =======================
__device__ __forceinline__ uint32_t smem_u32(const void* p) {
    uint32_t a;
    asm("{ .reg .u64 t; cvta.to.shared.u64 t, %1; cvt.u32.u64 %0, t; }" : "=r"(a) : "l"(p));
    return a;
}
__device__ __forceinline__ void cpa16(uint32_t dst, const void* src) {
    asm volatile("cp.async.cg.shared.global [%0], [%1], 16;" :: "r"(dst), "l"(src));
}
#define CP_COMMIT() asm volatile("cp.async.commit_group;" ::: "memory")
#define CP_WAIT(n)  asm volatile("cp.async.wait_group %0;" :: "n"(n) : "memory")

#define LDSM4(r0, r1, r2, r3, a) \
    asm volatile("ldmatrix.sync.aligned.m8n8.x4.shared.b16 {%0,%1,%2,%3}, [%4];" \
                 : "=r"(r0), "=r"(r1), "=r"(r2), "=r"(r3) : "r"(a))

__device__ __forceinline__ void mma16816(float* c, const uint32_t* a, uint32_t b0, uint32_t b1) {
    asm volatile(
        "mma.sync.aligned.m16n8k16.row.col.f32.f16.f16.f32 "
        "{%0,%1,%2,%3}, {%4,%5,%6,%7}, {%8,%9}, {%0,%1,%2,%3};"
        : "+f"(c[0]), "+f"(c[1]), "+f"(c[2]), "+f"(c[3])
        : "r"(a[0]), "r"(a[1]), "r"(a[2]), "r"(a[3]), "r"(b0), "r"(b1));
}

// ======================= common tile constants =======================
// CTA tile 128x256 (full N), 16 warps (4 M x 4 N), warp tile 32x64. KC=64, 3-stage ring.
static constexpr int BM = 128, KC = 64;
static constexpr int NCH = 512 / KC;            // 8 chunks
static constexpr int RSTRIDE = 144;             // 128B data + 16B pad; ldsm conflict-free
static constexpr int A_TILE  = 128 * RSTRIDE;   // 18432 B
static constexpr int W_TILE  = 256 * RSTRIDE;   // 36864 B (all 256 W rows)
static constexpr int STAGE_B = A_TILE + W_TILE; // 55296 B
static constexpr int NSTG = 3;
static constexpr int SMEM_BYTES = NSTG * STAGE_B;  // 165888 B -> 1 CTA/SM, 16 warps

// ======================= level GEMM (fp16 mma.sync, full-N CTA) =======================
// out[M,256] = tanh(A[M,512] @ W[256,512]^T + bias), fp16 in/out, fp32 accum.
// A traffic: each row tile read ONCE (vs twice with N-split grids).
template <bool GATHER>
__global__ void __launch_bounds__(512, 1)
mma_level(const __half* __restrict__ Ain,
          const int* __restrict__ tokens, const float* __restrict__ embed,
          const float* __restrict__ bias, __half* __restrict__ Out) {
    extern __shared__ char sm[];
    __shared__ int stok[256];
    const uint32_t smb = smem_u32(sm);

    const int tid  = threadIdx.x;
    const int wid  = tid >> 5;                    // 0..15
    const int lane = tid & 31;
    const int g    = lane >> 2;
    const int t    = lane & 3;
    const int m0 = (wid & 3) * 32;                // 4 warps along M
    const int n0 = (wid >> 2) * 64;               // 4 warps along N (full 256)
    const int rowBase = blockIdx.x * BM;
    const int kso = (wid & 1) * 2;                // ks stagger

    // ---- hoisted fill addressing: A 1024 units (2/thr), W 2048 units (4/thr) ----
    const int u   = tid & 7;
    const int r0f = tid >> 3;                     // 0..63; rows r0f + 64*i
    const __half* aSrc = GATHER ? nullptr
                                : Ain + (size_t)(rowBase + r0f) * 512 + u * 8;
    const __half* wSrc = g_W + (size_t)r0f * 512 + u * 8;
    const uint32_t dstOff = (uint32_t)r0f * RSTRIDE + u * 16;

    if (GATHER) {
        if (tid < 256) {
            int r = tid >> 1, j = tid & 1;
            int m = rowBase + r;
            stok[tid] = __ldg(&tokens[((m >> 8) << 9) + ((m & 255) << 1) + j]);
        }
        __syncthreads();
    }

    // ---- hoisted ldsm addressing ----
    const uint32_t lrow = lane & 15;
    const uint32_t lcol = (uint32_t)(lane >> 4) << 4;
    const uint32_t aOff = (uint32_t)(m0 + lrow) * RSTRIDE + lcol;
    const uint32_t wOff = A_TILE + (uint32_t)(n0 + lrow) * RSTRIDE + lcol;

    auto fill = [&](int c, int s) {
        if (GATHER) {
            // A: gather from fp32 embed table, convert, STS (visible after next barrier)
#pragma unroll
            for (int i = 0; i < 2; ++i) {
                int tok = stok[(r0f + 64 * i) * 2 + (c >> 2)];
                const float4* src = reinterpret_cast<const float4*>(
                    embed + (size_t)tok * 256 + (c & 3) * 64 + u * 8);
                float4 v0 = __ldg(src);
                float4 v1 = __ldg(src + 1);
                __half2 h0 = __floats2half2_rn(v0.x, v0.y);
                __half2 h1 = __floats2half2_rn(v0.z, v0.w);
                __half2 h2 = __floats2half2_rn(v1.x, v1.y);
                __half2 h3 = __floats2half2_rn(v1.z, v1.w);
                uint4 pk;
                pk.x = *reinterpret_cast<uint32_t*>(&h0);
                pk.y = *reinterpret_cast<uint32_t*>(&h1);
                pk.z = *reinterpret_cast<uint32_t*>(&h2);
                pk.w = *reinterpret_cast<uint32_t*>(&h3);
                *reinterpret_cast<uint4*>(sm + s * STAGE_B + dstOff + i * 64 * RSTRIDE) = pk;
            }
        } else {
#pragma unroll
            for (int i = 0; i < 2; ++i)
                cpa16(smb + s * STAGE_B + dstOff + i * 64 * RSTRIDE,
                      aSrc + i * 32768 + c * 64);
        }
#pragma unroll
        for (int i = 0; i < 4; ++i)
            cpa16(smb + s * STAGE_B + A_TILE + dstOff + i * 64 * RSTRIDE,
                  wSrc + i * 32768 + c * 64);
        CP_COMMIT();
    };

    float acc[2][8][4];
#pragma unroll
    for (int mt = 0; mt < 2; ++mt)
#pragma unroll
        for (int nt = 0; nt < 8; ++nt)
#pragma unroll
            for (int j = 0; j < 4; ++j) acc[mt][nt][j] = 0.0f;

    fill(0, 0);
    fill(1, 1);

#pragma unroll
    for (int c = 0; c < NCH; ++c) {
        if (c < NCH - 1) { CP_WAIT(1); } else { CP_WAIT(0); }
        __syncthreads();
        if (!GATHER && c + 2 < NCH) fill(c + 2, (c + 2) % NSTG);

        const uint32_t sb = smb + (c % NSTG) * STAGE_B;
#pragma unroll
        for (int ks2 = 0; ks2 < 4; ++ks2) {
            const int ks = (ks2 + kso) & 3;
            uint32_t a[2][4], b[16];
#pragma unroll
            for (int mt = 0; mt < 2; ++mt)
                LDSM4(a[mt][0], a[mt][1], a[mt][2], a[mt][3],
                      sb + aOff + ks * 32 + mt * 16 * RSTRIDE);
#pragma unroll
            for (int q = 0; q < 4; ++q)
                LDSM4(b[q * 4], b[q * 4 + 1], b[q * 4 + 2], b[q * 4 + 3],
                      sb + wOff + ks * 32 + q * 16 * RSTRIDE);
#pragma unroll
            for (int nt = 0; nt < 8; ++nt) {
                const uint32_t b0 = b[(nt >> 1) * 4 + (nt & 1)];
                const uint32_t b1 = b[(nt >> 1) * 4 + (nt & 1) + 2];
#pragma unroll
                for (int mt = 0; mt < 2; ++mt)
                    mma16816(acc[mt][nt], a[mt], b0, b1);
            }
        }

        if (GATHER && c + 2 < NCH) fill(c + 2, (c + 2) % NSTG);
    }

    // ---- epilogue: +bias, tanh, fp16 store ----
#pragma unroll
    for (int mt = 0; mt < 2; ++mt) {
#pragma unroll
        for (int nt = 0; nt < 8; ++nt) {
            const int col = n0 + nt * 8 + 2 * t;
            const float b0 = __ldg(&bias[col]);
            const float b1 = __ldg(&bias[col + 1]);
#pragma unroll
            for (int h = 0; h < 2; ++h) {
                const int row = rowBase + m0 + mt * 16 + g + h * 8;
                float v0 = tanhf(acc[mt][nt][2 * h]     + b0);
                float v1 = tanhf(acc[mt][nt][2 * h + 1] + b1);
                *reinterpret_cast<__half2*>(Out + (size_t)row * 256 + col) =
                    __floats2half2_rn(v0, v1);
            }
        }
    }
}

// ======================= fp16 weight conversion (one-time) =======================
__global__ void __launch_bounds__(256)
weight_split(const float* __restrict__ W) {
    int i = blockIdx.x * 256 + threadIdx.x;        // 131072 elems
    g_W[i] = __float2half_rn(W[i]);
}

// ======================= head =======================
__global__ void __launch_bounds__(256)
head_kernel(const __half* __restrict__ root,      // [256, 256] fp16
            const float* __restrict__ WF, const float* __restrict__ bF,
            const float* __restrict__ WO, const float* __restrict__ bO,
            float* __restrict__ out) {
    __shared__ float r[256];
    __shared__ float h[256];
    int b = blockIdx.x, t = threadIdx.x;
    r[t] = __half2float(root[b * 256 + t]);
    __syncthreads();
    float acc = bF[t];
    const float* w = WF + (size_t)t * 256;
#pragma unroll 8
    for (int d = 0; d < 256; d += 4) {
        float4 w4 = *reinterpret_cast<const float4*>(w + d);
        acc += r[d] * w4.x + r[d + 1] * w4.y + r[d + 2] * w4.z + r[d + 3] * w4.w;
    }
    h[t] = fmaxf(acc, 0.0f);
    __syncthreads();
    int wid = t >> 5, lane = t & 31;
    if (wid < 5) {
        float s = 0.0f;
        for (int i = lane; i < 256; i += 32) s += h[i] * WO[wid * 256 + i];
#pragma unroll
        for (int o = 16; o; o >>= 1) s += __shfl_down_sync(0xffffffffu, s, o);
        if (lane == 0) out[b * 5 + wid] = s + bO[wid];
    }
}

// ======================= launch =======================
extern "C" void kernel_launch(void* const* d_in, const int* in_sizes, int n_in,
                              void* d_out, int out_size) {
    (void)in_sizes; (void)n_in; (void)out_size;
    const int*   tokens = (const int*)  d_in[0];
    const float* embed  = (const float*)d_in[1];
    const float* WR_w   = (const float*)d_in[2];
    const float* WR_b   = (const float*)d_in[3];
    const float* WF_w   = (const float*)d_in[4];
    const float* WF_b   = (const float*)d_in[5];
    const float* WO_w   = (const float*)d_in[6];
    const float* WO_b   = (const float*)d_in[7];
    float* out = (float*)d_out;

    cudaFuncSetAttribute(mma_level<true>,  cudaFuncAttributeMaxDynamicSharedMemorySize, SMEM_BYTES);
    cudaFuncSetAttribute(mma_level<false>, cudaFuncAttributeMaxDynamicSharedMemorySize, SMEM_BYTES);

    __half *A, *B;
    cudaGetSymbolAddress((void**)&A, g_A);
    cudaGetSymbolAddress((void**)&B, g_B);

    weight_split<<<512, 256>>>(WR_w);

    // level 0: fused fp32-embedding gather, out -> g_A
    mma_level<true><<<65536 / BM, 512, SMEM_BYTES>>>(nullptr, tokens, embed, WR_b, A);

    // levels 1..8: ping-pong  (odd: A->B, even: B->A); lvl8 out -> g_A
    for (int lvl = 1; lvl <= 8; ++lvl) {
        int M = 65536 >> lvl;
        const __half* in = (lvl & 1) ? A : B;
        __half*       ot = (lvl & 1) ? B : A;
        mma_level<false><<<M / BM, 512, SMEM_BYTES>>>(in, nullptr, nullptr, WR_b, ot);
    }
    // root in g_A: [256, 256]
    head_kernel<<<256, 256>>>(A, WF_w, WF_b, WO_w, WO_b, out);
}

// round 16
// speedup vs baseline: 1.7797x; 1.7797x over previous
#include <cuda_runtime.h>
#include <cuda_fp16.h>
#include <cstdint>
#include <cstddef>
#include <math.h>

// ======================= device-global scratch (no allocs allowed) =======================
__device__ __align__(256) __half g_A[16777216];   // activations ping, 65536x256 max
__device__ __align__(256) __half g_B[16777216];   // activations pong
__device__ __align__(256) __half g_W[131072];     // WR_w fp16 [256,512]

// ======================= helpers =======================
__device__ __forceinline__ uint32_t smem_u32(const void* p) {
    uint32_t a;
    asm("{ .reg .u64 t; cvta.to.shared.u64 t, %1; cvt.u32.u64 %0, t; }" : "=r"(a) : "l"(p));
    return a;
}
__device__ __forceinline__ void cpa16(uint32_t dst, const void* src) {
    asm volatile("cp.async.cg.shared.global [%0], [%1], 16;" :: "r"(dst), "l"(src));
}
#define CP_COMMIT() asm volatile("cp.async.commit_group;" ::: "memory")
#define CP_WAIT(n)  asm volatile("cp.async.wait_group %0;" :: "n"(n) : "memory")

#define LDSM4(r0, r1, r2, r3, a) \
    asm volatile("ldmatrix.sync.aligned.m8n8.x4.shared.b16 {%0,%1,%2,%3}, [%4];" \
                 : "=r"(r0), "=r"(r1), "=r"(r2), "=r"(r3) : "r"(a))

__device__ __forceinline__ void mma16816(float* c, const uint32_t* a, uint32_t b0, uint32_t b1) {
    asm volatile(
        "mma.sync.aligned.m16n8k16.row.col.f32.f16.f16.f32 "
        "{%0,%1,%2,%3}, {%4,%5,%6,%7}, {%8,%9}, {%0,%1,%2,%3};"
        : "+f"(c[0]), "+f"(c[1]), "+f"(c[2]), "+f"(c[3])
        : "r"(a[0]), "r"(a[1]), "r"(a[2]), "r"(a[3]), "r"(b0), "r"(b1));
}

// ======================= common tile constants (round-9 champion config) =======================
static constexpr int BM = 128, BN = 128, KC = 64;
static constexpr int NCH = 512 / KC;            // 8 chunks
static constexpr int RSTRIDE = 144;             // 128B data + 16B pad; ldsm conflict-free
static constexpr int TILE_B  = 128 * RSTRIDE;   // 18432 B
static constexpr int STAGE_B = 2 * TILE_B;      // A + W
static constexpr int NSTG = 3;
static constexpr int SMEM_BYTES = NSTG * STAGE_B;  // 110592 B -> 2 CTAs/SM

// ======================= level GEMM (single-term fp16 mma.sync) =======================
// out[M,256] = tanh(A[M,512] @ W[256,512]^T + bias), fp16 in/out, fp32 accum.
// CTA 128x128, 8 warps (4 M x 2 N), warp tile 32x64. KC=64, 3-stage cp.async ring.
template <bool GATHER>
__global__ void __launch_bounds__(256, 2)
mma_level(const __half* __restrict__ Ain,
          const int* __restrict__ tokens, const float* __restrict__ embed,
          const float* __restrict__ bias, __half* __restrict__ Out) {
    extern __shared__ char sm[];
    __shared__ int stok[256];
    __shared__ float biasS[128];
    const uint32_t smb = smem_u32(sm);

    const int tid  = threadIdx.x;
    const int wid  = tid >> 5;
    const int lane = tid & 31;
    const int g    = lane >> 2;
    const int t    = lane & 3;
    const int m0 = (wid & 3) * 32;
    const int n0 = (wid >> 2) * 64;
    const int rowBase = blockIdx.x * BM;
    const int nBase   = blockIdx.y * BN;
    const int kso  = (wid & 1) * 2;               // ks stagger: odd warps start at ks=2

    // stage bias once (read by epilogue long after the first barrier)
    if (tid < 128) biasS[tid] = __ldg(&bias[nBase + tid]);

    // ---- hoisted fill addressing: unit (i) has r = r0f + 32*i, same u for all i ----
    const int u   = tid & 7;
    const int r0f = tid >> 3;                        // 0..31
    const __half* aSrc = GATHER ? nullptr
                                : Ain + (size_t)(rowBase + r0f) * 512 + u * 8;
    const __half* wSrc = g_W + (size_t)(nBase + r0f) * 512 + u * 8;
    const uint32_t dstOff = (uint32_t)r0f * RSTRIDE + u * 16;

    int tkA[4], tkB[4];
    if (GATHER) {
        int r = tid >> 1, j = tid & 1;
        int m = rowBase + r;
        stok[tid] = __ldg(&tokens[((m >> 8) << 9) + ((m & 255) << 1) + j]);
        __syncthreads();
#pragma unroll
        for (int i = 0; i < 4; ++i) {
            tkA[i] = stok[(r0f + 32 * i) * 2];
            tkB[i] = stok[(r0f + 32 * i) * 2 + 1];
        }
    }

    // ---- hoisted ldsm addressing ----
    const uint32_t lrow = lane & 15;
    const uint32_t lcol = (uint32_t)(lane >> 4) << 4;
    const uint32_t aOff = (uint32_t)(m0 + lrow) * RSTRIDE + lcol;
    const uint32_t wOff = TILE_B + (uint32_t)(n0 + lrow) * RSTRIDE + lcol;

    auto fill = [&](int c, int s) {
        if (GATHER) {
            // A: gather from fp32 embed table, convert, STS (visible after next barrier)
#pragma unroll
            for (int i = 0; i < 4; ++i) {
                int tok = (c >= 4) ? tkB[i] : tkA[i];
                const float4* src = reinterpret_cast<const float4*>(
                    embed + (size_t)tok * 256 + (c & 3) * 64 + u * 8);
                float4 v0 = __ldg(src);
                float4 v1 = __ldg(src + 1);
                __half2 h0 = __floats2half2_rn(v0.x, v0.y);
                __half2 h1 = __floats2half2_rn(v0.z, v0.w);
                __half2 h2 = __floats2half2_rn(v1.x, v1.y);
                __half2 h3 = __floats2half2_rn(v1.z, v1.w);
                uint4 pk;
                pk.x = *reinterpret_cast<uint32_t*>(&h0);
                pk.y = *reinterpret_cast<uint32_t*>(&h1);
                pk.z = *reinterpret_cast<uint32_t*>(&h2);
                pk.w = *reinterpret_cast<uint32_t*>(&h3);
                *reinterpret_cast<uint4*>(sm + s * STAGE_B + dstOff + i * 32 * RSTRIDE) = pk;
            }
        } else {
#pragma unroll
            for (int i = 0; i < 4; ++i)
                cpa16(smb + s * STAGE_B + dstOff + i * 32 * RSTRIDE,
                      aSrc + i * 16384 + c * 64);
        }
#pragma unroll
        for (int i = 0; i < 4; ++i)
            cpa16(smb + s * STAGE_B + TILE_B + dstOff + i * 32 * RSTRIDE,
                  wSrc + i * 16384 + c * 64);
        CP_COMMIT();
    };

    float acc[2][8][4];
#pragma unroll
    for (int mt = 0; mt < 2; ++mt)
#pragma unroll
        for (int nt = 0; nt < 8; ++nt)
#pragma unroll
            for (int j = 0; j < 4; ++j) acc[mt][nt][j] = 0.0f;

    fill(0, 0);
    fill(1, 1);

#pragma unroll
    for (int c = 0; c < NCH; ++c) {
        if (c < NCH - 1) { CP_WAIT(1); } else { CP_WAIT(0); }
        __syncthreads();
        // regular levels: issue next-stage cp.async BEFORE MMAs (proven layout)
        if (!GATHER && c + 2 < NCH) fill(c + 2, (c + 2) % NSTG);

        const uint32_t sb = smb + (c % NSTG) * STAGE_B;
#pragma unroll
        for (int ks2 = 0; ks2 < 4; ++ks2) {
            const int ks = (ks2 + kso) & 3;       // staggered k16 order (accum-order free)
            uint32_t a[2][4];
            LDSM4(a[0][0], a[0][1], a[0][2], a[0][3], sb + aOff + ks * 32);
            LDSM4(a[1][0], a[1][1], a[1][2], a[1][3], sb + aOff + ks * 32 + 16 * RSTRIDE);
#pragma unroll
            for (int half = 0; half < 2; ++half) {
                uint32_t b[8];
                LDSM4(b[0], b[1], b[2], b[3], sb + wOff + ks * 32 + half * 32 * RSTRIDE);
                LDSM4(b[4], b[5], b[6], b[7], sb + wOff + ks * 32 + (half * 32 + 16) * RSTRIDE);
#pragma unroll
                for (int jj = 0; jj < 2; ++jj) {
#pragma unroll
                    for (int sub = 0; sub < 2; ++sub) {
                        const int nt = half * 4 + jj * 2 + sub;
                        const uint32_t b0 = b[jj * 4 + sub], b1 = b[jj * 4 + sub + 2];
                        mma16816(acc[0][nt], a[0], b0, b1);
                        mma16816(acc[1][nt], a[1], b0, b1);
                    }
                }
            }
        }

        // gather level: fill AFTER MMAs so the synchronous LDG chain overlaps compute
        if (GATHER && c + 2 < NCH) fill(c + 2, (c + 2) % NSTG);
    }

    // ---- epilogue: +bias (smem), tanh, fp16 store ----
#pragma unroll
    for (int mt = 0; mt < 2; ++mt) {
#pragma unroll
        for (int nt = 0; nt < 8; ++nt) {
            const int colL = n0 + nt * 8 + 2 * t;
            const float b0 = biasS[colL];
            const float b1 = biasS[colL + 1];
#pragma unroll
            for (int h = 0; h < 2; ++h) {
                const int row = rowBase + m0 + mt * 16 + g + h * 8;
                float v0 = tanhf(acc[mt][nt][2 * h]     + b0);
                float v1 = tanhf(acc[mt][nt][2 * h + 1] + b1);
                *reinterpret_cast<__half2*>(Out + (size_t)row * 256 + nBase + colL) =
                    __floats2half2_rn(v0, v1);
            }
        }
    }
}

// ======================= fp16 weight conversion (one-time, vectorized) =======================
__global__ void __launch_bounds__(256)
weight_split(const float* __restrict__ W) {
    int base = (blockIdx.x * 256 + threadIdx.x) * 8;   // 131072 elems / 8 = 16384 threads
    const float4* s = reinterpret_cast<const float4*>(W + base);
    float4 v0 = s[0], v1 = s[1];
    __half2 h0 = __floats2half2_rn(v0.x, v0.y);
    __half2 h1 = __floats2half2_rn(v0.z, v0.w);
    __half2 h2 = __floats2half2_rn(v1.x, v1.y);
    __half2 h3 = __floats2half2_rn(v1.z, v1.w);
    uint4 pk;
    pk.x = *reinterpret_cast<uint32_t*>(&h0);
    pk.y = *reinterpret_cast<uint32_t*>(&h1);
    pk.z = *reinterpret_cast<uint32_t*>(&h2);
    pk.w = *reinterpret_cast<uint32_t*>(&h3);
    *reinterpret_cast<uint4*>(g_W + base) = pk;
}

// ======================= head =======================
__global__ void __launch_bounds__(256)
head_kernel(const __half* __restrict__ root,      // [256, 256] fp16
            const float* __restrict__ WF, const float* __restrict__ bF,
            const float* __restrict__ WO, const float* __restrict__ bO,
            float* __restrict__ out) {
    __shared__ float r[256];
    __shared__ float h[256];
    int b = blockIdx.x, t = threadIdx.x;
    r[t] = __half2float(root[b * 256 + t]);
    __syncthreads();
    float acc = bF[t];
    const float* w = WF + (size_t)t * 256;
#pragma unroll 8
    for (int d = 0; d < 256; d += 4) {
        float4 w4 = *reinterpret_cast<const float4*>(w + d);
        acc += r[d] * w4.x + r[d + 1] * w4.y + r[d + 2] * w4.z + r[d + 3] * w4.w;
    }
    h[t] = fmaxf(acc, 0.0f);
    __syncthreads();
    int wid = t >> 5, lane = t & 31;
    if (wid < 5) {
        float s = 0.0f;
        for (int i = lane; i < 256; i += 32) s += h[i] * WO[wid * 256 + i];
#pragma unroll
        for (int o = 16; o; o >>= 1) s += __shfl_down_sync(0xffffffffu, s, o);
        if (lane == 0) out[b * 5 + wid] = s + bO[wid];
    }
}

// ======================= launch =======================
extern "C" void kernel_launch(void* const* d_in, const int* in_sizes, int n_in,
                              void* d_out, int out_size) {
    (void)in_sizes; (void)n_in; (void)out_size;
    const int*   tokens = (const int*)  d_in[0];
    const float* embed  = (const float*)d_in[1];
    const float* WR_w   = (const float*)d_in[2];
    const float* WR_b   = (const float*)d_in[3];
    const float* WF_w   = (const float*)d_in[4];
    const float* WF_b   = (const float*)d_in[5];
    const float* WO_w   = (const float*)d_in[6];
    const float* WO_b   = (const float*)d_in[7];
    float* out = (float*)d_out;

    cudaFuncSetAttribute(mma_level<true>,  cudaFuncAttributeMaxDynamicSharedMemorySize, SMEM_BYTES);
    cudaFuncSetAttribute(mma_level<false>, cudaFuncAttributeMaxDynamicSharedMemorySize, SMEM_BYTES);

    __half *A, *B;
    cudaGetSymbolAddress((void**)&A, g_A);
    cudaGetSymbolAddress((void**)&B, g_B);

    weight_split<<<64, 256>>>(WR_w);

    // level 0: fused fp32-embedding gather, out -> g_A
    {
        dim3 grid(65536 / BM, 2);
        mma_level<true><<<grid, 256, SMEM_BYTES>>>(nullptr, tokens, embed, WR_b, A);
    }
    // levels 1..8: ping-pong  (odd: A->B, even: B->A); lvl8 out -> g_A
    for (int lvl = 1; lvl <= 8; ++lvl) {
        int M = 65536 >> lvl;
        dim3 grid(M / BM, 2);
        const __half* in = (lvl & 1) ? A : B;
        __half*       ot = (lvl & 1) ? B : A;
        mma_level<false><<<grid, 256, SMEM_BYTES>>>(in, nullptr, nullptr, WR_b, ot);
    }
    // root in g_A: [256, 256]
    head_kernel<<<256, 256>>>(A, WF_w, WF_b, WO_w, WO_b, out);
}